// round 3
// baseline (speedup 1.0000x reference)
#include <cuda_runtime.h>
#include <math.h>

#define B_     8
#define N_     4096
#define ALPHA  1.05f
#define JC     8              // j-dimension split factor
#define JCHUNK (N_ / JC)      // 512 candidates per block
#define PAIRS  (JCHUNK / 2)   // 256 candidate pairs

// Scratch (no device allocations allowed)
__device__ float g_part[B_ * N_ * JC * 6];  // partial sorted top-6 (reduced space)
__device__ float g_loss[B_];

// ---- f32x2 helpers (sm_100+ packed fp32; ptxas never auto-fuses these) ----
__device__ __forceinline__ unsigned long long pk2(float lo, float hi) {
    unsigned long long r;
    asm("mov.b64 %0, {%1, %2};" : "=l"(r) : "f"(lo), "f"(hi));
    return r;
}
__device__ __forceinline__ void upk2(unsigned long long v, float& lo, float& hi) {
    asm("mov.b64 {%0, %1}, %2;" : "=f"(lo), "=f"(hi) : "l"(v));
}
__device__ __forceinline__ unsigned long long fma2(unsigned long long a,
                                                   unsigned long long b,
                                                   unsigned long long c) {
    unsigned long long d;
    asm("fma.rn.f32x2 %0, %1, %2, %3;" : "=l"(d) : "l"(a), "l"(b), "l"(c));
    return d;
}

// Sorted top-6 insert (ascending b0..b5), d already known < b5.
#define INSERT6(d)                                          \
    do {                                                    \
        b5 = (d);                                           \
        float t_;                                           \
        t_ = fminf(b4, b5); b5 = fmaxf(b4, b5); b4 = t_;    \
        t_ = fminf(b3, b4); b4 = fmaxf(b3, b4); b3 = t_;    \
        t_ = fminf(b2, b3); b3 = fmaxf(b2, b3); b2 = t_;    \
        t_ = fminf(b1, b2); b2 = fmaxf(b1, b2); b1 = t_;    \
        t_ = fminf(b0, b1); b1 = fmaxf(b0, b1); b0 = t_;    \
    } while (0)

// ---------------------------------------------------------------------------
// Kernel 1: partial kNN in reduced-distance space r = ||pj||^2 - 2 pi.pj.
// Each block: 128 query points x 512-candidate chunk. Candidates are stored
// pair-interleaved so 3 fma.rn.f32x2 evaluate TWO candidates at once.
// ---------------------------------------------------------------------------
__global__ __launch_bounds__(128) void knn_part_kernel(const float* __restrict__ pc)
{
    __shared__ float4 spA[PAIRS];   // (x0, x1, y0, y1)
    __shared__ float4 spB[PAIRS];   // (z0, z1, w0, w1), w = |p|^2

    const int b  = blockIdx.z;
    const int jc = blockIdx.y;
    const float* __restrict__ p  = pc + (size_t)b * N_ * 3;
    const float* __restrict__ pj = p + (size_t)jc * JCHUNK * 3;

    for (int j = threadIdx.x; j < PAIRS; j += 128) {
        float x0 = __ldg(pj + 6 * j + 0), y0 = __ldg(pj + 6 * j + 1), z0 = __ldg(pj + 6 * j + 2);
        float x1 = __ldg(pj + 6 * j + 3), y1 = __ldg(pj + 6 * j + 4), z1 = __ldg(pj + 6 * j + 5);
        float w0 = fmaf(x0, x0, fmaf(y0, y0, z0 * z0));
        float w1 = fmaf(x1, x1, fmaf(y1, y1, z1 * z1));
        spA[j] = make_float4(x0, x1, y0, y1);
        spB[j] = make_float4(z0, z1, w0, w1);
    }
    __syncthreads();

    const int i  = blockIdx.x * 128 + threadIdx.x;
    const float xi = __ldg(p + 3 * i);
    const float yi = __ldg(p + 3 * i + 1);
    const float zi = __ldg(p + 3 * i + 2);
    const unsigned long long nx = pk2(-2.f * xi, -2.f * xi);
    const unsigned long long ny = pk2(-2.f * yi, -2.f * yi);
    const unsigned long long nz = pk2(-2.f * zi, -2.f * zi);

    const float INF = __int_as_float(0x7f800000);
    float b0 = INF, b1 = INF, b2 = INF, b3 = INF, b4 = INF, b5 = INF;

#pragma unroll 8
    for (int j = 0; j < PAIRS; ++j) {
        float4 a = spA[j];
        float4 c = spB[j];
        unsigned long long qx = pk2(a.x, a.y);
        unsigned long long qy = pk2(a.z, a.w);
        unsigned long long qz = pk2(c.x, c.y);
        unsigned long long qw = pk2(c.z, c.w);
        unsigned long long d2 = fma2(nx, qx, fma2(ny, qy, fma2(nz, qz, qw)));
        float dlo, dhi;
        upk2(d2, dlo, dhi);
        float mn = fminf(dlo, dhi);
        if (mn < b5) {                    // rare path
            if (dlo < b5) { INSERT6(dlo); }
            if (dhi < b5) { INSERT6(dhi); }
        }
    }

    float* __restrict__ out = g_part + (((size_t)b * N_ + i) * JC + jc) * 6;
    out[0] = b0; out[1] = b1; out[2] = b2;
    out[3] = b3; out[4] = b4; out[5] = b5;
}

// ---------------------------------------------------------------------------
// Kernel 2 (fused): merge 8 partial top-6 lists -> per-point value (+xx_i) ->
// per-batch mean/std(ddof=1) -> threshold -> masked mean * weight.
// ---------------------------------------------------------------------------
__global__ __launch_bounds__(512) void loss_kernel(const float* __restrict__ pc,
                                                   const float* __restrict__ weights)
{
    const int b   = blockIdx.x;
    const int tid = threadIdx.x;
    const float* __restrict__ p = pc + (size_t)b * N_ * 3;

    __shared__ float sval[N_];
    __shared__ float sh_a[16];
    __shared__ float sh_b[16];
    __shared__ float sh_thr;

    const float INF = __int_as_float(0x7f800000);

    // Merge: global top-6 = 6 smallest of JC*6 partial candidates (reduced
    // space), then value = mean(slots 1..5) + ||p_i||^2.
    for (int pt = tid; pt < N_; pt += 512) {
        const float* __restrict__ part = g_part + ((size_t)b * N_ + pt) * (JC * 6);
        float c0 = INF, c1 = INF, c2 = INF, c3 = INF, c4 = INF, c5 = INF;
        for (int t = 0; t < JC * 6; ++t) {
            float d = part[t];
            if (d < c5) {
                c5 = d;
                float u;
                u = fminf(c4, c5); c5 = fmaxf(c4, c5); c4 = u;
                u = fminf(c3, c4); c4 = fmaxf(c3, c4); c3 = u;
                u = fminf(c2, c3); c3 = fmaxf(c2, c3); c2 = u;
                u = fminf(c1, c2); c2 = fmaxf(c1, c2); c1 = u;
                u = fminf(c0, c1); c1 = fmaxf(c0, c1); c0 = u;
            }
        }
        float x = p[3 * pt], y = p[3 * pt + 1], z = p[3 * pt + 2];
        float xx = fmaf(x, x, fmaf(y, y, z * z));
        sval[pt] = (c1 + c2 + c3 + c4 + c5) * 0.2f + xx;
    }
    __syncthreads();

    // Pass 1: sum and sum of squares.
    float s = 0.f, s2 = 0.f;
    for (int t = tid; t < N_; t += 512) {
        float x = sval[t];
        s  += x;
        s2 = fmaf(x, x, s2);
    }
#pragma unroll
    for (int o = 16; o > 0; o >>= 1) {
        s  += __shfl_down_sync(0xffffffffu, s,  o);
        s2 += __shfl_down_sync(0xffffffffu, s2, o);
    }
    if ((tid & 31) == 0) { sh_a[tid >> 5] = s; sh_b[tid >> 5] = s2; }
    __syncthreads();
    if (tid < 32) {
        s  = (tid < 16) ? sh_a[tid] : 0.f;
        s2 = (tid < 16) ? sh_b[tid] : 0.f;
#pragma unroll
        for (int o = 8; o > 0; o >>= 1) {
            s  += __shfl_down_sync(0xffffffffu, s,  o);
            s2 += __shfl_down_sync(0xffffffffu, s2, o);
        }
        if (tid == 0) {
            float mean = s / (float)N_;
            float var  = (s2 - s * s / (float)N_) / (float)(N_ - 1);
            var = fmaxf(var, 0.f);
            sh_thr = mean + ALPHA * sqrtf(var);
        }
    }
    __syncthreads();

    // Pass 2: masked sum (value > threshold).
    const float thr = sh_thr;
    float m = 0.f;
    for (int t = tid; t < N_; t += 512) {
        float x = sval[t];
        if (x > thr) m += x;
    }
#pragma unroll
    for (int o = 16; o > 0; o >>= 1)
        m += __shfl_down_sync(0xffffffffu, m, o);
    if ((tid & 31) == 0) sh_a[tid >> 5] = m;
    __syncthreads();
    if (tid < 32) {
        m = (tid < 16) ? sh_a[tid] : 0.f;
#pragma unroll
        for (int o = 8; o > 0; o >>= 1)
            m += __shfl_down_sync(0xffffffffu, m, o);
        if (tid == 0)
            g_loss[b] = (m / (float)N_) * __ldg(weights + b);
    }
}

// ---------------------------------------------------------------------------
// Kernel 3: mean over batches -> scalar output.
// ---------------------------------------------------------------------------
__global__ void final_kernel(float* __restrict__ out)
{
    float s = 0.f;
#pragma unroll
    for (int b = 0; b < B_; ++b) s += g_loss[b];
    out[0] = s / (float)B_;
}

extern "C" void kernel_launch(void* const* d_in, const int* in_sizes, int n_in,
                              void* d_out, int out_size)
{
    const float* pc      = (const float*)d_in[0];  // [8, 4096, 3] f32
    const float* weights = (const float*)d_in[1];  // [8] f32
    float* out = (float*)d_out;

    dim3 grid1(N_ / 128, JC, B_);   // 32 x 8 x 8 = 2048 blocks
    knn_part_kernel<<<grid1, 128>>>(pc);
    loss_kernel<<<B_, 512>>>(pc, weights);
    final_kernel<<<1, 1>>>(out);
}

// round 4
// speedup vs baseline: 1.9137x; 1.9137x over previous
#include <cuda_runtime.h>
#include <math.h>

#define B_     8
#define N_     4096
#define ALPHA  1.05f
#define JC     4               // j-dimension split factor
#define JCHUNK (N_ / JC)       // 1024 candidates per block
#define PAIRS  (JCHUNK / 2)    // 512 candidate pairs

// Scratch (no device allocations allowed)
// Transposed partial layout: g_part[((b*JC + jc)*6 + slot) * N_ + i]
__device__ float g_part[B_ * JC * 6 * N_];
__device__ float g_value[B_ * N_];
__device__ float g_loss[B_];

// ---- f32x2 helpers ---------------------------------------------------------
// Pack only in STAGING (once per candidate), never in the hot loop.
__device__ __forceinline__ double pk2d(float lo, float hi) {
    double d;
    asm("mov.b64 %0, {%1, %2};" : "=d"(d) : "f"(lo), "f"(hi));
    return d;
}
__device__ __forceinline__ void upk2(unsigned long long v, float& lo, float& hi) {
    asm("mov.b64 {%0, %1}, %2;" : "=f"(lo), "=f"(hi) : "l"(v));
}
__device__ __forceinline__ unsigned long long fma2(unsigned long long a,
                                                   unsigned long long b,
                                                   unsigned long long c) {
    unsigned long long d;
    asm("fma.rn.f32x2 %0, %1, %2, %3;" : "=l"(d) : "l"(a), "l"(b), "l"(c));
    return d;
}

// Sorted top-6 insert (ascending b0..b5); caller guarantees d < b5.
#define INSERT6(d)                                          \
    do {                                                    \
        b5 = (d);                                           \
        float t_;                                           \
        t_ = fminf(b4, b5); b5 = fmaxf(b4, b5); b4 = t_;    \
        t_ = fminf(b3, b4); b4 = fmaxf(b3, b4); b3 = t_;    \
        t_ = fminf(b2, b3); b3 = fmaxf(b2, b3); b2 = t_;    \
        t_ = fminf(b1, b2); b2 = fmaxf(b1, b2); b1 = t_;    \
        t_ = fminf(b0, b1); b1 = fmaxf(b0, b1); b0 = t_;    \
    } while (0)

// ---------------------------------------------------------------------------
// Kernel 1: partial kNN in reduced space r = ||pj||^2 - 2 pi.pj (a per-i
// constant shift of the true distance, so top-6 ordering is unchanged).
// Candidates are PRE-PACKED pairwise in smem so the hot loop runs three
// fma.rn.f32x2 per TWO candidates with zero pack MOVs.
// ---------------------------------------------------------------------------
__global__ __launch_bounds__(128) void knn_part_kernel(const float* __restrict__ pc)
{
    __shared__ double2 sA[PAIRS];   // ((x0,x1), (y0,y1))  8 KB
    __shared__ double2 sB[PAIRS];   // ((z0,z1), (w0,w1))  8 KB, w = |p|^2

    const int b  = blockIdx.z;
    const int jc = blockIdx.y;
    const float* __restrict__ p  = pc + (size_t)b * N_ * 3;
    const float* __restrict__ pj = p + (size_t)jc * JCHUNK * 3;

    for (int j = threadIdx.x; j < PAIRS; j += 128) {
        float x0 = __ldg(pj + 6 * j + 0), y0 = __ldg(pj + 6 * j + 1), z0 = __ldg(pj + 6 * j + 2);
        float x1 = __ldg(pj + 6 * j + 3), y1 = __ldg(pj + 6 * j + 4), z1 = __ldg(pj + 6 * j + 5);
        float w0 = fmaf(x0, x0, fmaf(y0, y0, z0 * z0));
        float w1 = fmaf(x1, x1, fmaf(y1, y1, z1 * z1));
        sA[j] = make_double2(pk2d(x0, x1), pk2d(y0, y1));
        sB[j] = make_double2(pk2d(z0, z1), pk2d(w0, w1));
    }
    __syncthreads();

    const int i  = blockIdx.x * 128 + threadIdx.x;
    const float xi = __ldg(p + 3 * i);
    const float yi = __ldg(p + 3 * i + 1);
    const float zi = __ldg(p + 3 * i + 2);
    const unsigned long long nx = __double_as_longlong(pk2d(-2.f * xi, -2.f * xi));
    const unsigned long long ny = __double_as_longlong(pk2d(-2.f * yi, -2.f * yi));
    const unsigned long long nz = __double_as_longlong(pk2d(-2.f * zi, -2.f * zi));

    const float INF = __int_as_float(0x7f800000);
    float b0 = INF, b1 = INF, b2 = INF, b3 = INF, b4 = INF, b5 = INF;

#pragma unroll 8
    for (int j = 0; j < PAIRS; ++j) {
        double2 a = sA[j];
        double2 c = sB[j];
        unsigned long long d2 =
            fma2(nx, __double_as_longlong(a.x),
            fma2(ny, __double_as_longlong(a.y),
            fma2(nz, __double_as_longlong(c.x),
                     __double_as_longlong(c.y))));
        float dlo, dhi;
        upk2(d2, dlo, dhi);
        if (fminf(dlo, dhi) < b5) {           // rare (warp-coherent early)
            if (dlo < b5) { INSERT6(dlo); }
            if (dhi < b5) { INSERT6(dhi); }
        }
    }

    // Transposed, fully coalesced partial store.
    float* __restrict__ out = g_part + ((size_t)(b * JC + jc) * 6) * N_ + i;
    out[0 * N_] = b0; out[1 * N_] = b1; out[2 * N_] = b2;
    out[3 * N_] = b3; out[4 * N_] = b4; out[5 * N_] = b5;
}

// ---------------------------------------------------------------------------
// Kernel 2: parallel merge — one thread per point. 24 coalesced loads,
// top-6 of them, drop smallest (self), add back ||p_i||^2.
// ---------------------------------------------------------------------------
__global__ __launch_bounds__(256) void merge_kernel(const float* __restrict__ pc)
{
    const int gid = blockIdx.x * 256 + threadIdx.x;   // b*N + i
    const int b   = gid >> 12;
    const int i   = gid & (N_ - 1);

    const float INF = __int_as_float(0x7f800000);
    float c0 = INF, c1 = INF, c2 = INF, c3 = INF, c4 = INF, c5 = INF;

#pragma unroll
    for (int t = 0; t < JC * 6; ++t) {
        float d = g_part[((size_t)(b * JC * 6 + t)) * N_ + i];
        if (d < c5) {
            c5 = d;
            float u;
            u = fminf(c4, c5); c5 = fmaxf(c4, c5); c4 = u;
            u = fminf(c3, c4); c4 = fmaxf(c3, c4); c3 = u;
            u = fminf(c2, c3); c3 = fmaxf(c2, c3); c2 = u;
            u = fminf(c1, c2); c2 = fmaxf(c1, c2); c1 = u;
            u = fminf(c0, c1); c1 = fmaxf(c0, c1); c0 = u;
        }
    }
    const float* __restrict__ p = pc + (size_t)gid * 3;
    float x = __ldg(p), y = __ldg(p + 1), z = __ldg(p + 2);
    float xx = fmaf(x, x, fmaf(y, y, z * z));
    g_value[gid] = (c1 + c2 + c3 + c4 + c5) * 0.2f + xx;
}

// ---------------------------------------------------------------------------
// Kernel 3: per-batch mean/std(ddof=1) -> threshold -> masked mean * weight.
// ---------------------------------------------------------------------------
__global__ __launch_bounds__(512) void loss_kernel(const float* __restrict__ weights)
{
    const int b   = blockIdx.x;
    const int tid = threadIdx.x;
    const float* __restrict__ v = g_value + b * N_;

    __shared__ float sh_a[16];
    __shared__ float sh_b[16];
    __shared__ float sh_thr;

    float s = 0.f, s2 = 0.f;
    for (int t = tid; t < N_; t += 512) {
        float x = v[t];
        s  += x;
        s2 = fmaf(x, x, s2);
    }
#pragma unroll
    for (int o = 16; o > 0; o >>= 1) {
        s  += __shfl_down_sync(0xffffffffu, s,  o);
        s2 += __shfl_down_sync(0xffffffffu, s2, o);
    }
    if ((tid & 31) == 0) { sh_a[tid >> 5] = s; sh_b[tid >> 5] = s2; }
    __syncthreads();
    if (tid < 32) {
        s  = (tid < 16) ? sh_a[tid] : 0.f;
        s2 = (tid < 16) ? sh_b[tid] : 0.f;
#pragma unroll
        for (int o = 8; o > 0; o >>= 1) {
            s  += __shfl_down_sync(0xffffffffu, s,  o);
            s2 += __shfl_down_sync(0xffffffffu, s2, o);
        }
        if (tid == 0) {
            float mean = s / (float)N_;
            float var  = (s2 - s * s / (float)N_) / (float)(N_ - 1);
            var = fmaxf(var, 0.f);
            sh_thr = mean + ALPHA * sqrtf(var);
        }
    }
    __syncthreads();

    const float thr = sh_thr;
    float m = 0.f;
    for (int t = tid; t < N_; t += 512) {
        float x = v[t];
        if (x > thr) m += x;
    }
#pragma unroll
    for (int o = 16; o > 0; o >>= 1)
        m += __shfl_down_sync(0xffffffffu, m, o);
    if ((tid & 31) == 0) sh_a[tid >> 5] = m;
    __syncthreads();
    if (tid < 32) {
        m = (tid < 16) ? sh_a[tid] : 0.f;
#pragma unroll
        for (int o = 8; o > 0; o >>= 1)
            m += __shfl_down_sync(0xffffffffu, m, o);
        if (tid == 0)
            g_loss[b] = (m / (float)N_) * __ldg(weights + b);
    }
}

// ---------------------------------------------------------------------------
// Kernel 4: mean over batches -> scalar output.
// ---------------------------------------------------------------------------
__global__ void final_kernel(float* __restrict__ out)
{
    float s = 0.f;
#pragma unroll
    for (int b = 0; b < B_; ++b) s += g_loss[b];
    out[0] = s / (float)B_;
}

extern "C" void kernel_launch(void* const* d_in, const int* in_sizes, int n_in,
                              void* d_out, int out_size)
{
    const float* pc      = (const float*)d_in[0];  // [8, 4096, 3] f32
    const float* weights = (const float*)d_in[1];  // [8] f32
    float* out = (float*)d_out;

    dim3 grid1(N_ / 128, JC, B_);          // 32 x 4 x 8 = 1024 blocks
    knn_part_kernel<<<grid1, 128>>>(pc);
    merge_kernel<<<B_ * N_ / 256, 256>>>(pc);
    loss_kernel<<<B_, 512>>>(weights);
    final_kernel<<<1, 1>>>(out);
}